// round 2
// baseline (speedup 1.0000x reference)
#include <cuda_runtime.h>

// Problem constants
#define B_SAMPLES  4096
#define D_DIM      768
#define N_CLASSES  1000
#define MAX_STAGES 4
#define MAX_P      8
#define SHARED_P   16

#define D_VEC (D_DIM / 4)        // 192 float4 per row
#define CHUNKS 6                 // 192 float4 / 32 lanes

// Scratch (allocation-free): precomputed shared-stage means + per-sample descriptors
__device__ float g_shared_mean[MAX_STAGES * D_DIM];
__device__ int2  g_desc[B_SAMPLES];   // {pair_idx = cid*4+st, cnt}

// ---------------------------------------------------------------------------
// Prep kernel: grid = 20 blocks x 256 threads.
//   blocks 0..15 : pack descriptors (256 samples each)
//   blocks 16..19: shared_mean for stage (blockIdx-16), threads 0..191 active
// ---------------------------------------------------------------------------
__global__ __launch_bounds__(256)
void prep_kernel(const float* __restrict__ shared_protos,
                 const int*   __restrict__ class_ids,
                 const int*   __restrict__ stages,
                 const int*   __restrict__ proto_counts) {
    int blk = blockIdx.x;
    int t   = threadIdx.x;

    if (blk < 16) {
        int b = blk * 256 + t;                 // 0..4095
        int cid  = class_ids[b];
        int st   = stages[b];
        int pair = cid * MAX_STAGES + st;
        int cnt  = proto_counts[pair];
        g_desc[b] = make_int2(pair, cnt);
    } else {
        int st = blk - 16;                     // 0..3
        if (t < D_VEC) {
            const float4* src = reinterpret_cast<const float4*>(
                shared_protos + (size_t)st * SHARED_P * D_DIM);
            float4 acc = make_float4(0.f, 0.f, 0.f, 0.f);
#pragma unroll
            for (int p = 0; p < SHARED_P; ++p) {
                float4 x = src[p * D_VEC + t];
                acc.x += x.x; acc.y += x.y; acc.z += x.z; acc.w += x.w;
            }
            const float inv = 1.0f / (float)SHARED_P;
            acc.x *= inv; acc.y *= inv; acc.z *= inv; acc.w *= inv;
            reinterpret_cast<float4*>(g_shared_mean)[st * D_VEC + t] = acc;
        }
    }
}

// ---------------------------------------------------------------------------
// Main kernel: one warp per sample, each thread owns 6 float4 lanes of D.
// Up to 8 protos x 6 chunks = 48 independent LDG.128 per thread.
// ---------------------------------------------------------------------------
__global__ __launch_bounds__(256)
void proto_pool_kernel(const float* __restrict__ features,
                       const float* __restrict__ class_protos,
                       float* __restrict__ out) {
    int warp = (blockIdx.x * blockDim.x + threadIdx.x) >> 5;   // sample id
    int lane = threadIdx.x & 31;

    // Single 8-byte descriptor load (broadcast across the warp)
    int2 dd  = g_desc[warp];
    int pair = dd.x;
    int cnt  = dd.y;
    int st   = pair & 3;

    const float4* __restrict__ protos =
        reinterpret_cast<const float4*>(class_protos) +
        (size_t)pair * (MAX_P * D_VEC);

    float4 acc[CHUNKS];
#pragma unroll
    for (int c = 0; c < CHUNKS; ++c) acc[c] = make_float4(0.f, 0.f, 0.f, 0.f);

#pragma unroll
    for (int p = 0; p < MAX_P; ++p) {
        if (p < cnt) {
#pragma unroll
            for (int c = 0; c < CHUNKS; ++c) {
                float4 x = protos[p * D_VEC + c * 32 + lane];
                acc[c].x += x.x; acc[c].y += x.y;
                acc[c].z += x.z; acc[c].w += x.w;
            }
        }
    }

    float inv = 0.5f / (float)max(cnt, 1);   // fold the 0.5 into the mean

    const float4* __restrict__ feat =
        reinterpret_cast<const float4*>(features) + (size_t)warp * D_VEC;
    const float4* __restrict__ shm =
        reinterpret_cast<const float4*>(g_shared_mean) + st * D_VEC;
    float4* __restrict__ dst =
        reinterpret_cast<float4*>(out) + (size_t)warp * D_VEC;

#pragma unroll
    for (int c = 0; c < CHUNKS; ++c) {
        int v = c * 32 + lane;
        float4 f  = feat[v];
        float4 sh = shm[v];
        float4 r;
        r.x = f.x + 0.5f * sh.x + acc[c].x * inv;
        r.y = f.y + 0.5f * sh.y + acc[c].y * inv;
        r.z = f.z + 0.5f * sh.z + acc[c].z * inv;
        r.w = f.w + 0.5f * sh.w + acc[c].w * inv;
        dst[v] = r;
    }
}

extern "C" void kernel_launch(void* const* d_in, const int* in_sizes, int n_in,
                              void* d_out, int out_size) {
    const float* features      = (const float*)d_in[0];
    const float* class_protos  = (const float*)d_in[1];
    const float* shared_protos = (const float*)d_in[2];
    const int*   class_ids     = (const int*)d_in[3];
    const int*   stages        = (const int*)d_in[4];
    const int*   proto_counts  = (const int*)d_in[5];
    float* out = (float*)d_out;

    prep_kernel<<<20, 256>>>(shared_protos, class_ids, stages, proto_counts);
    // 4096 samples, 8 warps (samples) per 256-thread block -> 512 blocks
    proto_pool_kernel<<<B_SAMPLES / 8, 256>>>(features, class_protos, out);
}